// round 16
// baseline (speedup 1.0000x reference)
#include <cuda_runtime.h>
#include <cuda_fp16.h>

#define NN 100000
#define EE 1200000
#define HID 64
#define NG 256
#define OC 10
#define IN0 7

// ---- scratch (static device globals) ----
__device__ int   g_cnti[NN];
__device__ int   g_rowp[NN];
__device__ int   g_cursor[NN];
__device__ int   g_total;
__device__ int   g_csr[EE];                         // src only (4B records)
__device__ float g_dis[NN];
__device__ __align__(16) __half g_xph[NN * 8];      // fp16 dis[n]*x[n], 16B rows
__device__ __align__(256) __half g_hwh[NN * HID];   // prescaled fp16 rows (L1)
__device__ __align__(256) __half g_hwh2[NN * HID];  // prescaled fp16 rows (L2)
__device__ __align__(16) float g_sums[NG * HID];

// ---- histogram on dst, 4 edges/thread; spare duty: zero g_sums ----
__global__ void k_hist(const int* __restrict__ ei) {
    int tid = blockIdx.x * blockDim.x + threadIdx.x;
    if (tid < NG * HID) g_sums[tid] = 0.0f;
    if (tid == 0) g_total = 0;
    int e4 = tid * 4;
    if (e4 >= EE) return;
    int4 d = *(const int4*)&ei[EE + e4];
    atomicAdd(&g_cnti[d.x], 1);
    atomicAdd(&g_cnti[d.y], 1);
    atomicAdd(&g_cnti[d.z], 1);
    atomicAdd(&g_cnti[d.w], 1);
}

// ---- fused scan + dis + prescaled fp16 x rows ----
__global__ void k_scanA(const float* __restrict__ x) {
    __shared__ int sm[256];
    __shared__ int base_sm;
    int t = threadIdx.x;
    int i = blockIdx.x * 256 + t;
    int v = (i < NN) ? g_cnti[i] : 0;
    sm[t] = v;
    __syncthreads();
#pragma unroll
    for (int off = 1; off < 256; off <<= 1) {
        int add = (t >= off) ? sm[t - off] : 0;
        __syncthreads();
        sm[t] += add;
        __syncthreads();
    }
    if (t == 255) base_sm = atomicAdd(&g_total, sm[255]);
    __syncthreads();
    if (i < NN) {
        int r = base_sm + sm[t] - v;
        g_rowp[i] = r;
        g_cursor[i] = r;
        float d = rsqrtf((float)v + 1.0f);
        g_dis[i] = d;
        const float* xr = x + (long long)i * IN0;
        __half2 p0 = __floats2half2_rn(d * xr[0], d * xr[1]);
        __half2 p1 = __floats2half2_rn(d * xr[2], d * xr[3]);
        __half2 p2 = __floats2half2_rn(d * xr[4], d * xr[5]);
        __half2 p3 = __floats2half2_rn(d * xr[6], 0.0f);
        uint4 o;
        o.x = *(unsigned*)&p0; o.y = *(unsigned*)&p1;
        o.z = *(unsigned*)&p2; o.w = *(unsigned*)&p3;
        *(uint4*)(g_xph + (long long)i * 8) = o;
    }
}

// ---- fill CSR (src only), 4 edges/thread ----
__global__ void k_fill(const int* __restrict__ ei) {
    int e4 = (blockIdx.x * blockDim.x + threadIdx.x) * 4;
    if (e4 >= EE) return;
    int4 s = *(const int4*)&ei[e4];
    int4 d = *(const int4*)&ei[EE + e4];
    int p0 = atomicAdd(&g_cursor[d.x], 1);
    int p1 = atomicAdd(&g_cursor[d.y], 1);
    int p2 = atomicAdd(&g_cursor[d.z], 1);
    int p3 = atomicAdd(&g_cursor[d.w], 1);
    g_csr[p0] = s.x;
    g_csr[p1] = s.y;
    g_csr[p2] = s.z;
    g_csr[p3] = s.w;
}

// ---- helpers ----
__device__ __forceinline__ void unpack8(uint4 u, float* f) {
    const __half2* h = (const __half2*)&u;
#pragma unroll
    for (int j = 0; j < 4; j++) {
        float2 p = __half22float2(h[j]);
        f[2 * j] = p.x;
        f[2 * j + 1] = p.y;
    }
}

// Warp-local mm64: lane j of each 8-lane node-group holds h[8] = channels
// [8j,8j+8). Computes o[c] = sum_k relu-free h[k]*W[k][c] for c in [8j,8j+8)
// via shfl broadcast of h across the group. No block barrier.
__device__ __forceinline__ void warp_mm64(const float* __restrict__ Ws,
                                          const float h[8], float o[8],
                                          int lane, int j) {
#pragma unroll
    for (int i = 0; i < 8; i++) o[i] = 0.0f;
#pragma unroll
    for (int k = 0; k < HID; k++) {
        int src = (lane & 24) | (k >> 3);
        float hv = __shfl_sync(0xffffffffu, h[k & 7], src);
        const float4* wr = (const float4*)&Ws[k * HID + j * 8];
        float4 wa = wr[0], wb = wr[1];
        o[0] += hv * wa.x; o[1] += hv * wa.y; o[2] += hv * wa.z; o[3] += hv * wa.w;
        o[4] += hv * wb.x; o[5] += hv * wb.y; o[6] += hv * wb.z; o[7] += hv * wb.w;
    }
}

__device__ __forceinline__ void pack_store(__half* dst, const float o[8],
                                           float dn, int j) {
    __half2 p0 = __floats2half2_rn(dn * o[0], dn * o[1]);
    __half2 p1 = __floats2half2_rn(dn * o[2], dn * o[3]);
    __half2 p2 = __floats2half2_rn(dn * o[4], dn * o[5]);
    __half2 p3 = __floats2half2_rn(dn * o[6], dn * o[7]);
    uint4 u;
    u.x = *(unsigned*)&p0; u.y = *(unsigned*)&p1;
    u.z = *(unsigned*)&p2; u.w = *(unsigned*)&p3;
    *((uint4*)dst + j) = u;
}

// ---- gm7mm: gather x + mm7(+b0) + relu + warp mm64(W1) -> hwh fp16 ----
// 32 nodes x 8 lanes; NN % 32 == 0 so all blocks full.
__global__ void __launch_bounds__(256) k_gm7mm(const float* __restrict__ W0,
                                               const float* __restrict__ b0,
                                               const float* __restrict__ W1) {
    __shared__ float W1s[HID * HID];   // 16 KB
    __shared__ float W0s[IN0 * HID];
    __shared__ float b0s[HID];
    int t = threadIdx.x;
    for (int i = t; i < HID * HID / 4; i += 256)
        ((float4*)W1s)[i] = ((const float4*)W1)[i];
    if (t < IN0 * 16) ((float4*)W0s)[t] = ((const float4*)W0)[t];
    if (t < 16) ((float4*)b0s)[t] = ((const float4*)b0)[t];
    __syncthreads();                      // fixed-point sync, before gathers
    int nl = t >> 3, j = t & 7, lane = t & 31;
    int n = blockIdx.x * 32 + nl;
    int s0 = g_rowp[n], deg = g_cnti[n];
    float acc[8];
#pragma unroll
    for (int i = 0; i < 8; i++) acc[i] = 0.0f;
    for (int e = s0 + j; e < s0 + deg; e += 8) {
        int s = g_csr[e];
        uint4 v = *(const uint4*)(g_xph + (long long)s * 8);
        float f[8];
        unpack8(v, f);
#pragma unroll
        for (int i = 0; i < 8; i++) acc[i] += f[i];
    }
    unsigned m = 0xffffffffu;
#pragma unroll
    for (int o = 1; o < 8; o <<= 1) {
#pragma unroll
        for (int i = 0; i < 8; i++) acc[i] += __shfl_xor_sync(m, acc[i], o);
    }
    uint4 sv = *(const uint4*)(g_xph + (long long)n * 8);
    float sf[8];
    unpack8(sv, sf);
    float dn = g_dis[n];
    float xin[8];
#pragma unroll
    for (int i = 0; i < 8; i++) xin[i] = dn * (acc[i] + sf[i]);
    // mm7 + bias + relu -> h (channels [8j,8j+8) in regs)
    float h[8];
#pragma unroll
    for (int i = 0; i < 8; i++) h[i] = b0s[j * 8 + i];
#pragma unroll
    for (int k = 0; k < IN0; k++) {
        float hv = xin[k];
#pragma unroll
        for (int i = 0; i < 8; i++) h[i] += hv * W0s[k * HID + j * 8 + i];
    }
#pragma unroll
    for (int i = 0; i < 8; i++) h[i] = fmaxf(h[i], 0.0f);
    // warp-local mm64(W1), prescale by dis, store fp16
    float o[8];
    warp_mm64(W1s, h, o, lane, j);
    pack_store(g_hwh + (long long)n * HID, o, dn, j);
}

// ---- gathmm: gather hwh(+b1) + relu + warp mm64(W2) -> hwh2 fp16 ----
__global__ void __launch_bounds__(256) k_gathmm(const float* __restrict__ b1,
                                                const float* __restrict__ W2) {
    __shared__ float W2s[HID * HID];   // 16 KB
    __shared__ float b1s[HID];
    int t = threadIdx.x;
    for (int i = t; i < HID * HID / 4; i += 256)
        ((float4*)W2s)[i] = ((const float4*)W2)[i];
    if (t < 16) ((float4*)b1s)[t] = ((const float4*)b1)[t];
    __syncthreads();
    int nl = t >> 3, j = t & 7, lane = t & 31;
    int n = blockIdx.x * 32 + nl;
    int s0 = g_rowp[n], deg = g_cnti[n];
    float acc[8], acc2[8], tmp[8];
    uint4 self = ((const uint4*)(g_hwh + (long long)n * HID))[j];
    unpack8(self, acc);
#pragma unroll
    for (int i = 0; i < 8; i++) acc2[i] = 0.0f;
    int e = s0, end = s0 + deg;
    for (; e + 1 < end; e += 2) {
        int sa = g_csr[e], sb = g_csr[e + 1];
        uint4 v0 = ((const uint4*)(g_hwh + (long long)sa * HID))[j];
        uint4 v1 = ((const uint4*)(g_hwh + (long long)sb * HID))[j];
        float f0[8], f1[8];
        unpack8(v0, f0); unpack8(v1, f1);
#pragma unroll
        for (int i = 0; i < 8; i++) acc[i] += f0[i];
#pragma unroll
        for (int i = 0; i < 8; i++) acc2[i] += f1[i];
    }
    if (e < end) {
        uint4 v0 = ((const uint4*)(g_hwh + (long long)g_csr[e] * HID))[j];
        unpack8(v0, tmp);
#pragma unroll
        for (int i = 0; i < 8; i++) acc[i] += tmp[i];
    }
    float dn = g_dis[n];
    float h[8];
#pragma unroll
    for (int i = 0; i < 8; i++)
        h[i] = fmaxf(dn * (acc[i] + acc2[i]) + b1s[j * 8 + i], 0.0f);
    float o[8];
    warp_mm64(W2s, h, o, lane, j);
    pack_store(g_hwh2 + (long long)n * HID, o, dn, j);
}

// ---- gatherpool: (dis[n]*(sum hw2'+self') + b2) pooled into g_sums ----
__global__ void __launch_bounds__(256) k_gatherpool(const float* __restrict__ b2,
                                                    const int* __restrict__ batch) {
    int t = threadIdx.x;
    int lane = t & 31;
    int n = blockIdx.x * 32 + (t >> 3);
    int q = t & 7;
    float r[8];
#pragma unroll
    for (int i = 0; i < 8; i++) r[i] = 0.0f;
    int g = batch[(n < NN) ? n : (NN - 1)];
    if (n < NN) {
        int s0 = g_rowp[n], deg = g_cnti[n];
        float acc[8], acc2[8], tmp[8];
        uint4 self = ((const uint4*)(g_hwh2 + (long long)n * HID))[q];
        unpack8(self, acc);
#pragma unroll
        for (int i = 0; i < 8; i++) acc2[i] = 0.0f;
        int e = s0, end = s0 + deg;
        for (; e + 1 < end; e += 2) {
            int sa = g_csr[e], sb = g_csr[e + 1];
            uint4 v0 = ((const uint4*)(g_hwh2 + (long long)sa * HID))[q];
            uint4 v1 = ((const uint4*)(g_hwh2 + (long long)sb * HID))[q];
            float f0[8], f1[8];
            unpack8(v0, f0); unpack8(v1, f1);
#pragma unroll
            for (int i = 0; i < 8; i++) acc[i] += f0[i];
#pragma unroll
            for (int i = 0; i < 8; i++) acc2[i] += f1[i];
        }
        if (e < end) {
            uint4 v0 = ((const uint4*)(g_hwh2 + (long long)g_csr[e] * HID))[q];
            unpack8(v0, tmp);
#pragma unroll
            for (int i = 0; i < 8; i++) acc[i] += tmp[i];
        }
        float dn = g_dis[n];
        float4 b0 = ((const float4*)b2)[q * 2];
        float4 b1 = ((const float4*)b2)[q * 2 + 1];
        r[0] = dn * (acc[0] + acc2[0]) + b0.x; r[1] = dn * (acc[1] + acc2[1]) + b0.y;
        r[2] = dn * (acc[2] + acc2[2]) + b0.z; r[3] = dn * (acc[3] + acc2[3]) + b0.w;
        r[4] = dn * (acc[4] + acc2[4]) + b1.x; r[5] = dn * (acc[5] + acc2[5]) + b1.y;
        r[6] = dn * (acc[6] + acc2[6]) + b1.z; r[7] = dn * (acc[7] + acc2[7]) + b1.w;
    }
    unsigned m = 0xffffffffu;
    int g0 = __shfl_sync(m, g, lane & 7);
    bool allsame = __all_sync(m, g == g0);
    if (allsame) {
#pragma unroll
        for (int i = 0; i < 8; i++) {
            r[i] += __shfl_xor_sync(m, r[i], 8);
            r[i] += __shfl_xor_sync(m, r[i], 16);
        }
        if (lane < 8) {
            float4* sp = (float4*)&g_sums[g * HID + q * 8];
            atomicAdd(sp, make_float4(r[0], r[1], r[2], r[3]));
            atomicAdd(sp + 1, make_float4(r[4], r[5], r[6], r[7]));
        }
    } else {
        float4* sp = (float4*)&g_sums[g * HID + q * 8];
        atomicAdd(sp, make_float4(r[0], r[1], r[2], r[3]));
        atomicAdd(sp + 1, make_float4(r[4], r[5], r[6], r[7]));
    }
}

// ---- final linear; counts via binary search on sorted batch ----
__global__ void k_fin(const int* __restrict__ batch,
                      const float* __restrict__ lw,
                      const float* __restrict__ lb,
                      float* __restrict__ out) {
    int g = threadIdx.x;
    if (g >= NG) return;
    int lo = 0, hi = NN;
    while (lo < hi) { int mid = (lo + hi) >> 1; if (batch[mid] < g) lo = mid + 1; else hi = mid; }
    int start = lo;
    lo = start; hi = NN;
    while (lo < hi) { int mid = (lo + hi) >> 1; if (batch[mid] < g + 1) lo = mid + 1; else hi = mid; }
    float cnt = (float)(lo - start);
    float inv = 1.0f / fmaxf(cnt, 1.0f);
    float acc[OC];
#pragma unroll
    for (int o = 0; o < OC; o++) acc[o] = lb[o];
    for (int k = 0; k < HID; k++) {
        float v = g_sums[g * HID + k] * inv;
#pragma unroll
        for (int o = 0; o < OC; o++) acc[o] += v * lw[k * OC + o];
    }
#pragma unroll
    for (int o = 0; o < OC; o++) out[g * OC + o] = acc[o];
}

extern "C" void kernel_launch(void* const* d_in, const int* in_sizes, int n_in,
                              void* d_out, int out_size) {
    const float* x   = (const float*)d_in[0];
    const int* ei    = (const int*)d_in[1];
    const int* bat   = (const int*)d_in[2];
    const float* W0  = (const float*)d_in[3];
    const float* b0  = (const float*)d_in[4];
    const float* W1  = (const float*)d_in[5];
    const float* b1  = (const float*)d_in[6];
    const float* W2  = (const float*)d_in[7];
    const float* b2  = (const float*)d_in[8];
    const float* lw  = (const float*)d_in[9];
    const float* lb  = (const float*)d_in[10];
    float* out       = (float*)d_out;

    const int TB = 256;
    int g32_grid = (NN + 31) / 32;
    int e4_grid = (EE / 4 + TB - 1) / TB;

    int* cnti_ptr = nullptr;
    cudaGetSymbolAddress((void**)&cnti_ptr, g_cnti);
    cudaMemsetAsync(cnti_ptr, 0, NN * sizeof(int));

    k_hist<<<e4_grid, TB>>>(ei);                  // hist + zero g_sums/g_total
    k_scanA<<<(NN + 255) / 256, 256>>>(x);        // scan + dis + fp16 xp rows
    k_fill<<<e4_grid, TB>>>(ei);                  // src-only CSR

    k_gm7mm<<<g32_grid, TB>>>(W0, b0, W1);        // layer0 + mm(W1) -> hwh
    k_gathmm<<<g32_grid, TB>>>(b1, W2);           // gather + mm(W2) -> hwh2
    k_gatherpool<<<g32_grid, TB>>>(b2, bat);      // gather + pool -> sums
    k_fin<<<1, TB>>>(bat, lw, lb, out);
}

// round 17
// speedup vs baseline: 1.3255x; 1.3255x over previous
#include <cuda_runtime.h>
#include <cuda_fp16.h>

#define NN 100000
#define EE 1200000
#define HID 64
#define NG 256
#define OC 10
#define IN0 7
#define CSRMAX (EE + 3 * NN + 8)

// ---- scratch (static device globals) ----
__device__ int   g_cnti[NN];
__device__ int   g_rowp[NN];
__device__ int   g_cursor[NN];
__device__ int   g_total;
__device__ int   g_csr[CSRMAX];                        // src (pad = NN)
__device__ float g_dis[NN];
__device__ __align__(16) __half g_xph[(NN + 1) * 8];   // fp16 dis*x rows
__device__ __align__(256) __half g_hwh[(NN + 1) * HID];// prescaled fp16 rows; row NN = 0
__device__ __align__(16) __half g_hh[NN * HID];        // fp16 relu(hidden)
__device__ __align__(16) float g_sums[NG * HID];

// ---- histogram on dst, 4 edges/thread; spare: zero sums + pad rows ----
__global__ void k_hist(const int* __restrict__ ei) {
    int tid = blockIdx.x * blockDim.x + threadIdx.x;
    if (tid < NG * HID) g_sums[tid] = 0.0f;
    if (tid == 0) g_total = 0;
    if (tid < 8) ((uint4*)(g_hwh + (long long)NN * HID))[tid] = make_uint4(0, 0, 0, 0);
    if (tid == 8) *(uint4*)(g_xph + (long long)NN * 8) = make_uint4(0, 0, 0, 0);
    int e4 = tid * 4;
    if (e4 >= EE) return;
    int4 d = *(const int4*)&ei[EE + e4];
    atomicAdd(&g_cnti[d.x], 1);
    atomicAdd(&g_cnti[d.y], 1);
    atomicAdd(&g_cnti[d.z], 1);
    atomicAdd(&g_cnti[d.w], 1);
}

// ---- fused scan (over 4-padded sizes) + dis + fp16 x rows + csr padding ----
__global__ void k_scanA(const float* __restrict__ x) {
    __shared__ int sm[256];
    __shared__ int base_sm;
    int t = threadIdx.x;
    int i = blockIdx.x * 256 + t;
    int deg = (i < NN) ? g_cnti[i] : 0;
    int degp = (deg + 3) & ~3;
    sm[t] = degp;
    __syncthreads();
#pragma unroll
    for (int off = 1; off < 256; off <<= 1) {
        int add = (t >= off) ? sm[t - off] : 0;
        __syncthreads();
        sm[t] += add;
        __syncthreads();
    }
    if (t == 255) base_sm = atomicAdd(&g_total, sm[255]);
    __syncthreads();
    if (i < NN) {
        int r = base_sm + sm[t] - degp;
        g_rowp[i] = r;
        g_cursor[i] = r;
        for (int p = r + deg; p < r + degp; p++) g_csr[p] = NN;  // zero-row pads
        float d = rsqrtf((float)deg + 1.0f);
        g_dis[i] = d;
        const float* xr = x + (long long)i * IN0;
        __half2 p0 = __floats2half2_rn(d * xr[0], d * xr[1]);
        __half2 p1 = __floats2half2_rn(d * xr[2], d * xr[3]);
        __half2 p2 = __floats2half2_rn(d * xr[4], d * xr[5]);
        __half2 p3 = __floats2half2_rn(d * xr[6], 0.0f);
        uint4 o;
        o.x = *(unsigned*)&p0; o.y = *(unsigned*)&p1;
        o.z = *(unsigned*)&p2; o.w = *(unsigned*)&p3;
        *(uint4*)(g_xph + (long long)i * 8) = o;
    }
}

// ---- fill CSR (src only), 4 edges/thread ----
__global__ void k_fill(const int* __restrict__ ei) {
    int e4 = (blockIdx.x * blockDim.x + threadIdx.x) * 4;
    if (e4 >= EE) return;
    int4 s = *(const int4*)&ei[e4];
    int4 d = *(const int4*)&ei[EE + e4];
    int p0 = atomicAdd(&g_cursor[d.x], 1);
    int p1 = atomicAdd(&g_cursor[d.y], 1);
    int p2 = atomicAdd(&g_cursor[d.z], 1);
    int p3 = atomicAdd(&g_cursor[d.w], 1);
    g_csr[p0] = s.x;
    g_csr[p1] = s.y;
    g_csr[p2] = s.z;
    g_csr[p3] = s.w;
}

// ---- helpers ----
__device__ __forceinline__ void unpack8(uint4 u, float* f) {
    const __half2* h = (const __half2*)&u;
#pragma unroll
    for (int j = 0; j < 4; j++) {
        float2 p = __half22float2(h[j]);
        f[2 * j] = p.x;
        f[2 * j + 1] = p.y;
    }
}
__device__ __forceinline__ void acc8(float* a, const float* f) {
#pragma unroll
    for (int i = 0; i < 8; i++) a[i] += f[i];
}

// ---- gm7: lane-per-edge gather of fp16 x + mm7(+b0) + relu -> g_hh fp16 ----
// 32 nodes x 8 lanes; NN % 32 == 0.
__global__ void __launch_bounds__(256) k_gm7(const float* __restrict__ W0,
                                             const float* __restrict__ b0) {
    __shared__ float W0s[IN0 * HID];
    __shared__ float b0s[HID];
    int t = threadIdx.x;
    if (t < IN0 * 16) ((float4*)W0s)[t] = ((const float4*)W0)[t];
    if (t < 16) ((float4*)b0s)[t] = ((const float4*)b0)[t];
    __syncthreads();
    int nl = t >> 3, j = t & 7;
    int n = blockIdx.x * 32 + nl;
    int s0 = g_rowp[n], deg = g_cnti[n];
    float acc[8];
#pragma unroll
    for (int i = 0; i < 8; i++) acc[i] = 0.0f;
    for (int e = s0 + j; e < s0 + deg; e += 8) {
        int s = g_csr[e];
        uint4 v = *(const uint4*)(g_xph + (long long)s * 8);
        float f[8];
        unpack8(v, f);
        acc8(acc, f);
    }
    unsigned m = 0xffffffffu;
#pragma unroll
    for (int o = 1; o < 8; o <<= 1) {
#pragma unroll
        for (int i = 0; i < 8; i++) acc[i] += __shfl_xor_sync(m, acc[i], o);
    }
    uint4 sv = *(const uint4*)(g_xph + (long long)n * 8);
    float sf[8];
    unpack8(sv, sf);
    float dn = g_dis[n];
    float xin[8];
#pragma unroll
    for (int i = 0; i < 8; i++) xin[i] = dn * (acc[i] + sf[i]);
    float s[8];
#pragma unroll
    for (int i = 0; i < 8; i++) s[i] = b0s[j * 8 + i];
#pragma unroll
    for (int k = 0; k < IN0; k++) {
        float hv = xin[k];
#pragma unroll
        for (int i = 0; i < 8; i++) s[i] += hv * W0s[k * HID + j * 8 + i];
    }
    __half2 q0 = __floats2half2_rn(fmaxf(s[0], 0.f), fmaxf(s[1], 0.f));
    __half2 q1 = __floats2half2_rn(fmaxf(s[2], 0.f), fmaxf(s[3], 0.f));
    __half2 q2 = __floats2half2_rn(fmaxf(s[4], 0.f), fmaxf(s[5], 0.f));
    __half2 q3 = __floats2half2_rn(fmaxf(s[6], 0.f), fmaxf(s[7], 0.f));
    uint4 u;
    u.x = *(unsigned*)&q0; u.y = *(unsigned*)&q1;
    u.z = *(unsigned*)&q2; u.w = *(unsigned*)&q3;
    ((uint4*)(g_hh + (long long)n * HID))[j] = u;
}

// ---- mm64: g_hwh = fp16( dis[n] * (g_hh[n] @ W) ), 64 nodes/block ----
// g_hh already relu'd.
__global__ void k_mm64(const float* __restrict__ W) {
    __shared__ float4 Ws4[HID * 16];
    __shared__ float4 hs4[16 * 16];
    int t = threadIdx.x;
#pragma unroll
    for (int i = 0; i < 4; i++) Ws4[t + 256 * i] = ((const float4*)W)[t + 256 * i];
    int nl = t >> 4;
    int q = t & 15;
#pragma unroll
    for (int g = 0; g < 4; g++) {
        int node = blockIdx.x * 64 + g * 16 + nl;
        float dn = (node < NN) ? g_dis[node] : 0.0f;
        __syncthreads();
        float4 v = make_float4(0.f, 0.f, 0.f, 0.f);
        if (node < NN) {
            uint2 u = ((const uint2*)(g_hh + (long long)node * HID))[q];
            float2 a = __half22float2(*(const __half2*)&u.x);
            float2 b = __half22float2(*(const __half2*)&u.y);
            v = make_float4(a.x, a.y, b.x, b.y);
        }
        hs4[nl * 16 + q] = v;
        __syncthreads();
        if (node < NN) {
            const float* hrow = (const float*)&hs4[nl * 16];
            float4 sv = make_float4(0.f, 0.f, 0.f, 0.f);
#pragma unroll
            for (int k = 0; k < HID; k++) {
                float hv = hrow[k];
                float4 w = Ws4[k * 16 + q];
                sv.x += hv * w.x; sv.y += hv * w.y; sv.z += hv * w.z; sv.w += hv * w.w;
            }
            __half2 h0 = __floats2half2_rn(dn * sv.x, dn * sv.y);
            __half2 h1 = __floats2half2_rn(dn * sv.z, dn * sv.w);
            uint2 o;
            o.x = *(unsigned*)&h0;
            o.y = *(unsigned*)&h1;
            ((uint2*)(g_hwh + (long long)node * HID))[q] = o;
        }
    }
}

// ---- gather64h: g_hh = relu(dis*(sum hw' + self') + b1) fp16; 4-edge chunks ----
__global__ void __launch_bounds__(256) k_gather64h(const float* __restrict__ b) {
    int t = threadIdx.x;
    int n = blockIdx.x * 32 + (t >> 3);
    int q = t & 7;
    if (n >= NN) return;
    int s0 = g_rowp[n];
    int degp = (g_cnti[n] + 3) & ~3;
    float acc[8], acc2[8], tmp[8];
    uint4 self = ((const uint4*)(g_hwh + (long long)n * HID))[q];
    unpack8(self, acc);
#pragma unroll
    for (int i = 0; i < 8; i++) acc2[i] = 0.0f;
    for (int e = s0; e < s0 + degp; e += 4) {
        int4 cs = *(const int4*)&g_csr[e];
        uint4 v0 = ((const uint4*)(g_hwh + (long long)cs.x * HID))[q];
        uint4 v1 = ((const uint4*)(g_hwh + (long long)cs.y * HID))[q];
        uint4 v2 = ((const uint4*)(g_hwh + (long long)cs.z * HID))[q];
        uint4 v3 = ((const uint4*)(g_hwh + (long long)cs.w * HID))[q];
        unpack8(v0, tmp); acc8(acc, tmp);
        unpack8(v1, tmp); acc8(acc2, tmp);
        unpack8(v2, tmp); acc8(acc, tmp);
        unpack8(v3, tmp); acc8(acc2, tmp);
    }
    float dn = g_dis[n];
    float4 b0 = ((const float4*)b)[q * 2];
    float4 b1 = ((const float4*)b)[q * 2 + 1];
    float r[8];
    r[0] = fmaxf(dn * (acc[0] + acc2[0]) + b0.x, 0.f);
    r[1] = fmaxf(dn * (acc[1] + acc2[1]) + b0.y, 0.f);
    r[2] = fmaxf(dn * (acc[2] + acc2[2]) + b0.z, 0.f);
    r[3] = fmaxf(dn * (acc[3] + acc2[3]) + b0.w, 0.f);
    r[4] = fmaxf(dn * (acc[4] + acc2[4]) + b1.x, 0.f);
    r[5] = fmaxf(dn * (acc[5] + acc2[5]) + b1.y, 0.f);
    r[6] = fmaxf(dn * (acc[6] + acc2[6]) + b1.z, 0.f);
    r[7] = fmaxf(dn * (acc[7] + acc2[7]) + b1.w, 0.f);
    __half2 q0 = __floats2half2_rn(r[0], r[1]);
    __half2 q1 = __floats2half2_rn(r[2], r[3]);
    __half2 q2 = __floats2half2_rn(r[4], r[5]);
    __half2 q3 = __floats2half2_rn(r[6], r[7]);
    uint4 u;
    u.x = *(unsigned*)&q0; u.y = *(unsigned*)&q1;
    u.z = *(unsigned*)&q2; u.w = *(unsigned*)&q3;
    ((uint4*)(g_hh + (long long)n * HID))[q] = u;
}

// ---- gatherpool: (dis*(sum hw'+self') + b2) pooled into g_sums; 4-edge chunks ----
__global__ void __launch_bounds__(256) k_gatherpool(const float* __restrict__ b2,
                                                    const int* __restrict__ batch) {
    int t = threadIdx.x;
    int lane = t & 31;
    int n = blockIdx.x * 32 + (t >> 3);
    int q = t & 7;
    float r[8];
#pragma unroll
    for (int i = 0; i < 8; i++) r[i] = 0.0f;
    int g = batch[(n < NN) ? n : (NN - 1)];
    if (n < NN) {
        int s0 = g_rowp[n];
        int degp = (g_cnti[n] + 3) & ~3;
        float acc[8], acc2[8], tmp[8];
        uint4 self = ((const uint4*)(g_hwh + (long long)n * HID))[q];
        unpack8(self, acc);
#pragma unroll
        for (int i = 0; i < 8; i++) acc2[i] = 0.0f;
        for (int e = s0; e < s0 + degp; e += 4) {
            int4 cs = *(const int4*)&g_csr[e];
            uint4 v0 = ((const uint4*)(g_hwh + (long long)cs.x * HID))[q];
            uint4 v1 = ((const uint4*)(g_hwh + (long long)cs.y * HID))[q];
            uint4 v2 = ((const uint4*)(g_hwh + (long long)cs.z * HID))[q];
            uint4 v3 = ((const uint4*)(g_hwh + (long long)cs.w * HID))[q];
            unpack8(v0, tmp); acc8(acc, tmp);
            unpack8(v1, tmp); acc8(acc2, tmp);
            unpack8(v2, tmp); acc8(acc, tmp);
            unpack8(v3, tmp); acc8(acc2, tmp);
        }
        float dn = g_dis[n];
        float4 b0 = ((const float4*)b2)[q * 2];
        float4 b1 = ((const float4*)b2)[q * 2 + 1];
        r[0] = dn * (acc[0] + acc2[0]) + b0.x; r[1] = dn * (acc[1] + acc2[1]) + b0.y;
        r[2] = dn * (acc[2] + acc2[2]) + b0.z; r[3] = dn * (acc[3] + acc2[3]) + b0.w;
        r[4] = dn * (acc[4] + acc2[4]) + b1.x; r[5] = dn * (acc[5] + acc2[5]) + b1.y;
        r[6] = dn * (acc[6] + acc2[6]) + b1.z; r[7] = dn * (acc[7] + acc2[7]) + b1.w;
    }
    unsigned m = 0xffffffffu;
    int g0 = __shfl_sync(m, g, lane & 7);
    bool allsame = __all_sync(m, g == g0);
    if (allsame) {
#pragma unroll
        for (int i = 0; i < 8; i++) {
            r[i] += __shfl_xor_sync(m, r[i], 8);
            r[i] += __shfl_xor_sync(m, r[i], 16);
        }
        if (lane < 8) {
            float4* sp = (float4*)&g_sums[g * HID + q * 8];
            atomicAdd(sp, make_float4(r[0], r[1], r[2], r[3]));
            atomicAdd(sp + 1, make_float4(r[4], r[5], r[6], r[7]));
        }
    } else {
        float4* sp = (float4*)&g_sums[g * HID + q * 8];
        atomicAdd(sp, make_float4(r[0], r[1], r[2], r[3]));
        atomicAdd(sp + 1, make_float4(r[4], r[5], r[6], r[7]));
    }
}

// ---- final linear; counts via binary search on sorted batch ----
__global__ void k_fin(const int* __restrict__ batch,
                      const float* __restrict__ lw,
                      const float* __restrict__ lb,
                      float* __restrict__ out) {
    int g = threadIdx.x;
    if (g >= NG) return;
    int lo = 0, hi = NN;
    while (lo < hi) { int mid = (lo + hi) >> 1; if (batch[mid] < g) lo = mid + 1; else hi = mid; }
    int start = lo;
    lo = start; hi = NN;
    while (lo < hi) { int mid = (lo + hi) >> 1; if (batch[mid] < g + 1) lo = mid + 1; else hi = mid; }
    float cnt = (float)(lo - start);
    float inv = 1.0f / fmaxf(cnt, 1.0f);
    float acc[OC];
#pragma unroll
    for (int o = 0; o < OC; o++) acc[o] = lb[o];
    for (int k = 0; k < HID; k++) {
        float v = g_sums[g * HID + k] * inv;
#pragma unroll
        for (int o = 0; o < OC; o++) acc[o] += v * lw[k * OC + o];
    }
#pragma unroll
    for (int o = 0; o < OC; o++) out[g * OC + o] = acc[o];
}

extern "C" void kernel_launch(void* const* d_in, const int* in_sizes, int n_in,
                              void* d_out, int out_size) {
    const float* x   = (const float*)d_in[0];
    const int* ei    = (const int*)d_in[1];
    const int* bat   = (const int*)d_in[2];
    const float* W0  = (const float*)d_in[3];
    const float* b0  = (const float*)d_in[4];
    const float* W1  = (const float*)d_in[5];
    const float* b1  = (const float*)d_in[6];
    const float* W2  = (const float*)d_in[7];
    const float* b2  = (const float*)d_in[8];
    const float* lw  = (const float*)d_in[9];
    const float* lb  = (const float*)d_in[10];
    float* out       = (float*)d_out;

    const int TB = 256;
    int g32_grid = (NN + 31) / 32;
    int e4_grid = (EE / 4 + TB - 1) / TB;

    int* cnti_ptr = nullptr;
    cudaGetSymbolAddress((void**)&cnti_ptr, g_cnti);
    cudaMemsetAsync(cnti_ptr, 0, NN * sizeof(int));

    k_hist<<<e4_grid, TB>>>(ei);                  // hist + zero sums/pads
    k_scanA<<<(NN + 255) / 256, 256>>>(x);        // padded scan + dis + x rows
    k_fill<<<e4_grid, TB>>>(ei);                  // src-only CSR

    k_gm7<<<g32_grid, TB>>>(W0, b0);              // layer0 -> g_hh (fp16, relu)
    k_mm64<<<(NN + 63) / 64, TB>>>(W1);           // dis*(g_hh@W1) -> hwh
    k_gather64h<<<g32_grid, TB>>>(b1);            // gather -> g_hh (fp16, relu)
    k_mm64<<<(NN + 63) / 64, TB>>>(W2);           // dis*(g_hh@W2) -> hwh
    k_gatherpool<<<g32_grid, TB>>>(b2, bat);      // gather + pool -> sums
    k_fin<<<1, TB>>>(bat, lw, lb, out);
}